// round 14
// baseline (speedup 1.0000x reference)
#include <cuda_runtime.h>
#include <math.h>

#define N_NODES 100000
#define N_EDGES 1200000
#define F_IN 128
#define H 64
#define C 40
#define NB_SCAN 391   // ceil(100000/256)
#define G1_TILE 64
#define G1_GRID ((N_NODES + G1_TILE - 1) / G1_TILE)   // 1563
#define G1_SMEM ((F_IN * H + G1_TILE * F_IN) * 4)     // 65536 bytes
#define FIN_GRID ((N_NODES + 255) / 256)              // 391

// ---------------- scratch (device globals; no allocs allowed) ----------------
__device__ int   g_is64;
__device__ int   g_deg[N_NODES];
__device__ int   g_off[N_NODES];
__device__ int   g_cur[N_NODES];
__device__ int   g_bsum[NB_SCAN];
__device__ float g_dinv[N_NODES];
__device__ int   g_csrc[N_EDGES];
__device__ float g_h1[(size_t)N_NODES * H];   // x @ W1
__device__ float g_a1[(size_t)N_NODES * H];   // aggregated layer-1 (pre-bias)
__device__ float g_h2[(size_t)N_NODES * H];   // relu(a1+b1) @ W2

// ---------------- zero degrees + int64-vs-int32 detection ----------------
__global__ void k_pre(const void* ei) {
    int i = blockIdx.x * blockDim.x + threadIdx.x;
    if (i < N_NODES) g_deg[i] = 0;
    if (i == 0) {
        const long long* p = (const long long*)ei;
        int ok = 1;
        for (int t = 0; t < 64; ++t) {
            long long v = p[t];
            if (v < 0 || v >= N_NODES) { ok = 0; break; }
        }
        g_is64 = ok;
    }
}

__device__ __forceinline__ int load_idx(const void* ei, int pos, int which) {
    if (g_is64) return (int)((const long long*)ei)[(size_t)which * N_EDGES + pos];
    return ((const int*)ei)[(size_t)which * N_EDGES + pos];
}

__global__ void k_hist(const void* __restrict__ ei) {
    int e = blockIdx.x * blockDim.x + threadIdx.x;
    if (e < N_EDGES) atomicAdd(&g_deg[load_idx(ei, e, 1)], 1);
}

// ---------------- exclusive scan of degrees (3 kernels) + dinv ----------------
__global__ void __launch_bounds__(256) k_scan1() {
    int i = blockIdx.x * 256 + threadIdx.x;
    int v = (i < N_NODES) ? g_deg[i] : 0;
    int lane = threadIdx.x & 31, w = threadIdx.x >> 5;
    int incl = v;
#pragma unroll
    for (int o = 1; o < 32; o <<= 1) {
        int t = __shfl_up_sync(0xffffffffu, incl, o);
        if (lane >= o) incl += t;
    }
    __shared__ int ws[8];
    if (lane == 31) ws[w] = incl;
    __syncthreads();
    if (w == 0 && lane < 8) {
        int t = ws[lane];
        int inc = t;
#pragma unroll
        for (int o = 1; o < 8; o <<= 1) {
            int u = __shfl_up_sync(0xffu, inc, o);
            if (lane >= o) inc += u;
        }
        ws[lane] = inc - t;  // exclusive warp base
    }
    __syncthreads();
    int excl = incl - v + ws[w];
    if (i < N_NODES) {
        g_off[i] = excl;
        g_dinv[i] = rsqrtf((float)(v + 1));  // +1 self-loop
    }
    if (threadIdx.x == 255) g_bsum[blockIdx.x] = excl + v;
}

__global__ void __launch_bounds__(512) k_scan2() {
    __shared__ int buf[512];
    int t = threadIdx.x;
    int v = (t < NB_SCAN) ? g_bsum[t] : 0;
    buf[t] = v;
    __syncthreads();
    for (int o = 1; o < 512; o <<= 1) {
        int u = (t >= o) ? buf[t - o] : 0;
        __syncthreads();
        buf[t] += u;
        __syncthreads();
    }
    if (t < NB_SCAN) g_bsum[t] = buf[t] - v;  // exclusive
}

__global__ void __launch_bounds__(256) k_scan3() {
    int i = blockIdx.x * 256 + threadIdx.x;
    if (i < N_NODES) {
        int o = g_off[i] + g_bsum[blockIdx.x];
        g_off[i] = o;
        g_cur[i] = o;
    }
}

// ---------------- CSR scatter (int atomics only) ----------------
__global__ void k_scatter(const void* __restrict__ ei) {
    int e = blockIdx.x * blockDim.x + threadIdx.x;
    if (e < N_EDGES) {
        int s = load_idx(ei, e, 0);
        int d = load_idx(ei, e, 1);
        int pos = atomicAdd(&g_cur[d], 1);
        g_csrc[pos] = s;
    }
}

// ---------------- GEMM1: register-tiled 64x64 tile per CTA (proven) ----------
__global__ void __launch_bounds__(256) k_gemm1(const float* __restrict__ x,
                                               const float* __restrict__ W1) {
    extern __shared__ float dsm[];
    float* Ws = dsm;                 // 8192 floats
    float* xs = dsm + F_IN * H;      // 8192 floats

    int tid = threadIdx.x;
    int r0 = blockIdx.x * G1_TILE;

#pragma unroll
    for (int i = 0; i < (F_IN * H) / (256 * 4); ++i) {
        int idx = (i * 256 + tid) * 4;
        *(float4*)&Ws[idx] = *(const float4*)&W1[idx];
    }
#pragma unroll
    for (int i = 0; i < (G1_TILE * F_IN) / (256 * 4); ++i) {
        int t = i * 256 + tid;
        int row = t >> 5;
        int c4 = (t & 31) << 2;
        int r = r0 + row;
        float4 v = make_float4(0.f, 0.f, 0.f, 0.f);
        if (r < N_NODES) v = *(const float4*)&x[(size_t)r * F_IN + c4];
        *(float4*)&xs[row * F_IN + c4] = v;
    }
    __syncthreads();

    int ty = tid >> 4, tx = tid & 15;
    float acc[4][4] = {};

#pragma unroll 4
    for (int k4 = 0; k4 < F_IN / 4; ++k4) {
        float4 xv[4], wv[4];
#pragma unroll
        for (int i = 0; i < 4; ++i)
            xv[i] = *(const float4*)&xs[(ty * 4 + i) * F_IN + k4 * 4];
#pragma unroll
        for (int kk = 0; kk < 4; ++kk)
            wv[kk] = *(const float4*)&Ws[(k4 * 4 + kk) * H + tx * 4];
#pragma unroll
        for (int i = 0; i < 4; ++i) {
            float4 a = xv[i];
            acc[i][0] += a.x * wv[0].x + a.y * wv[1].x + a.z * wv[2].x + a.w * wv[3].x;
            acc[i][1] += a.x * wv[0].y + a.y * wv[1].y + a.z * wv[2].y + a.w * wv[3].y;
            acc[i][2] += a.x * wv[0].z + a.y * wv[1].z + a.z * wv[2].z + a.w * wv[3].z;
            acc[i][3] += a.x * wv[0].w + a.y * wv[1].w + a.z * wv[2].w + a.w * wv[3].w;
        }
    }

#pragma unroll
    for (int i = 0; i < 4; ++i) {
        int r = r0 + ty * 4 + i;
        if (r < N_NODES)
            *(float4*)&g_h1[(size_t)r * H + tx * 4] =
                make_float4(acc[i][0], acc[i][1], acc[i][2], acc[i][3]);
    }
}

// ---------------- agg1: pure aggregation (EXACT R2 edge loop, no smem) -------
__global__ void __launch_bounds__(256) k_agg1() {
    int tid = threadIdx.x;
    int w = tid >> 5, lane = tid & 31;
    int n = blockIdx.x * 8 + w;
    int c = lane << 1;

    float di = g_dinv[n];
    int row = g_off[n], deg = g_deg[n];

    float2 acc = *(const float2*)&g_h1[(size_t)n * H + c];
    float sl = di * di;
    acc.x *= sl; acc.y *= sl;

    const int* ep = g_csrc + row;
    for (int j = 0; j < deg; ++j) {
        int s = ep[j];
        float nm = g_dinv[s] * di;
        float2 v = *(const float2*)&g_h1[(size_t)s * H + c];
        acc.x += nm * v.x;
        acc.y += nm * v.y;
    }
    *(float2*)&g_a1[(size_t)n * H + c] = acc;
}

// ---------------- GEMM2: h2 = relu(a1 + b1) @ W2 (register-tiled) ------------
__global__ void __launch_bounds__(256) k_gemm2(const float* __restrict__ W2,
                                               const float* __restrict__ b1) {
    __shared__ float Ws[H * H];      // 16 KB
    __shared__ float as[G1_TILE * H];// 16 KB

    int tid = threadIdx.x;
    int r0 = blockIdx.x * G1_TILE;

#pragma unroll
    for (int i = 0; i < (H * H) / (256 * 4); ++i) {
        int idx = (i * 256 + tid) * 4;
        *(float4*)&Ws[idx] = *(const float4*)&W2[idx];
    }
#pragma unroll
    for (int i = 0; i < (G1_TILE * H) / (256 * 4); ++i) {
        int t = i * 256 + tid;
        int row = t >> 4;            // 16 float4 per row
        int c4 = (t & 15) << 2;
        int r = r0 + row;
        float4 v = make_float4(0.f, 0.f, 0.f, 0.f);
        if (r < N_NODES) {
            v = *(const float4*)&g_a1[(size_t)r * H + c4];
            float4 b = *(const float4*)&b1[c4];
            v.x = fmaxf(v.x + b.x, 0.f);
            v.y = fmaxf(v.y + b.y, 0.f);
            v.z = fmaxf(v.z + b.z, 0.f);
            v.w = fmaxf(v.w + b.w, 0.f);
        }
        *(float4*)&as[row * H + c4] = v;
    }
    __syncthreads();

    int ty = tid >> 4, tx = tid & 15;
    float acc[4][4] = {};

#pragma unroll 4
    for (int k4 = 0; k4 < H / 4; ++k4) {
        float4 xv[4], wv[4];
#pragma unroll
        for (int i = 0; i < 4; ++i)
            xv[i] = *(const float4*)&as[(ty * 4 + i) * H + k4 * 4];
#pragma unroll
        for (int kk = 0; kk < 4; ++kk)
            wv[kk] = *(const float4*)&Ws[(k4 * 4 + kk) * H + tx * 4];
#pragma unroll
        for (int i = 0; i < 4; ++i) {
            float4 a = xv[i];
            acc[i][0] += a.x * wv[0].x + a.y * wv[1].x + a.z * wv[2].x + a.w * wv[3].x;
            acc[i][1] += a.x * wv[0].y + a.y * wv[1].y + a.z * wv[2].y + a.w * wv[3].y;
            acc[i][2] += a.x * wv[0].z + a.y * wv[1].z + a.z * wv[2].z + a.w * wv[3].z;
            acc[i][3] += a.x * wv[0].w + a.y * wv[1].w + a.z * wv[2].w + a.w * wv[3].w;
        }
    }

#pragma unroll
    for (int i = 0; i < 4; ++i) {
        int r = r0 + ty * 4 + i;
        if (r < N_NODES)
            *(float4*)&g_h2[(size_t)r * H + tx * 4] =
                make_float4(acc[i][0], acc[i][1], acc[i][2], acc[i][3]);
    }
}

// ---------------- agg2: pure aggregation of h2 + b2 -> emb (in d_out) --------
__global__ void __launch_bounds__(256) k_agg2(const float* __restrict__ b2,
                                              float* __restrict__ out) {
    int tid = threadIdx.x;
    int w = tid >> 5, lane = tid & 31;
    int n = blockIdx.x * 8 + w;
    int c = lane << 1;

    float di = g_dinv[n];
    int row = g_off[n], deg = g_deg[n];

    float2 acc = *(const float2*)&g_h2[(size_t)n * H + c];
    float sl = di * di;
    acc.x *= sl; acc.y *= sl;

    const int* ep = g_csrc + row;
    for (int j = 0; j < deg; ++j) {
        int s = ep[j];
        float nm = g_dinv[s] * di;
        float2 v = *(const float2*)&g_h2[(size_t)s * H + c];
        acc.x += nm * v.x;
        acc.y += nm * v.y;
    }
    acc.x += __ldg(&b2[c]);
    acc.y += __ldg(&b2[c + 1]);

    float* emb = out + (size_t)N_NODES * C;
    *(float2*)&emb[(size_t)n * H + c] = acc;
}

// ---------------- final: thread-per-node classifier + softmax + argmax -------
__global__ void __launch_bounds__(256) k_final(const float* __restrict__ Wc,
                                               const float* __restrict__ bc,
                                               float* __restrict__ out) {
    __shared__ float WcS[H * C];  // 10.24 KB
    __shared__ float bcS[C];
    int tid = threadIdx.x;
    for (int i = tid; i < H * C; i += 256) WcS[i] = Wc[i];
    if (tid < C) bcS[tid] = bc[tid];
    __syncthreads();

    int n = blockIdx.x * 256 + tid;
    if (n >= N_NODES) return;

    const size_t embOff  = (size_t)N_NODES * C;
    const size_t softOff = embOff + (size_t)N_NODES * H;
    const size_t hardOff = softOff + (size_t)N_NODES * C;

    const float* emb = out + embOff + (size_t)n * H;

    float acc[C];
#pragma unroll
    for (int j = 0; j < C; ++j) acc[j] = bcS[j];

#pragma unroll 4
    for (int k4 = 0; k4 < H / 4; ++k4) {
        float4 e = *(const float4*)&emb[k4 * 4];
        const float* w0 = &WcS[(k4 * 4) * C];
#pragma unroll
        for (int j = 0; j < C; ++j)
            acc[j] += e.x * w0[j] + e.y * w0[C + j] + e.z * w0[2 * C + j]
                    + e.w * w0[3 * C + j];
    }

    // write logits
    float* lg = out + (size_t)n * C;
#pragma unroll
    for (int j4 = 0; j4 < C / 4; ++j4)
        *(float4*)&lg[j4 * 4] = make_float4(acc[j4 * 4], acc[j4 * 4 + 1],
                                            acc[j4 * 4 + 2], acc[j4 * 4 + 3]);

    // argmax (first-match, matches jnp.argmax)
    float mv = acc[0];
    int   mi = 0;
#pragma unroll
    for (int j = 1; j < C; ++j)
        if (acc[j] > mv) { mv = acc[j]; mi = j; }
    out[hardOff + n] = (float)mi;

    // softmax
    float s = 0.f;
#pragma unroll
    for (int j = 0; j < C; ++j) {
        acc[j] = __expf(acc[j] - mv);
        s += acc[j];
    }
    float inv = 1.0f / s;
    float* sf = out + softOff + (size_t)n * C;
#pragma unroll
    for (int j4 = 0; j4 < C / 4; ++j4)
        *(float4*)&sf[j4 * 4] = make_float4(acc[j4 * 4] * inv, acc[j4 * 4 + 1] * inv,
                                            acc[j4 * 4 + 2] * inv, acc[j4 * 4 + 3] * inv);
}

// ---------------- launch ----------------
extern "C" void kernel_launch(void* const* d_in, const int* in_sizes, int n_in,
                              void* d_out, int out_size) {
    const float* x  = (const float*)d_in[0];
    const void*  ei = d_in[1];
    const float* W1 = (const float*)d_in[2];
    const float* b1 = (const float*)d_in[3];
    const float* W2 = (const float*)d_in[4];
    const float* b2 = (const float*)d_in[5];
    const float* Wc = (const float*)d_in[6];
    const float* bc = (const float*)d_in[7];
    float* out = (float*)d_out;

    cudaFuncSetAttribute(k_gemm1, cudaFuncAttributeMaxDynamicSharedMemorySize,
                         G1_SMEM);

    k_pre<<<(N_NODES + 255) / 256, 256>>>(ei);          // 1
    k_hist<<<(N_EDGES + 255) / 256, 256>>>(ei);         // 2
    k_scan1<<<NB_SCAN, 256>>>();                        // 3
    k_gemm1<<<G1_GRID, 256, G1_SMEM>>>(x, W1);          // 4  <- profiled slot
    k_scan2<<<1, 512>>>();                              // 5
    k_scan3<<<NB_SCAN, 256>>>();                        // 6
    k_scatter<<<(N_EDGES + 255) / 256, 256>>>(ei);      // 7

    k_agg1<<<N_NODES / 8, 256>>>();                     // 8
    k_gemm2<<<G1_GRID, 256>>>(W2, b1);                  // 9
    k_agg2<<<N_NODES / 8, 256>>>(b2, out);              // 10
    k_final<<<FIN_GRID, 256>>>(Wc, bc, out);            // 11
}

// round 15
// speedup vs baseline: 1.1755x; 1.1755x over previous
#include <cuda_runtime.h>
#include <math.h>

#define N_NODES 100000
#define N_EDGES 1200000
#define F_IN 128
#define H 64
#define C 40
#define NB_SCAN 391   // ceil(100000/256)
#define G1_TILE 64
#define G1_GRID ((N_NODES + G1_TILE - 1) / G1_TILE)   // 1563
#define G1_SMEM ((F_IN * H + G1_TILE * F_IN) * 4)     // 65536 bytes

// ---------------- scratch (device globals; no allocs allowed) ----------------
__device__ int   g_is64;
__device__ int   g_deg[N_NODES];
__device__ int   g_off[N_NODES];
__device__ int   g_cur[N_NODES];
__device__ int   g_bsum[NB_SCAN];
__device__ float g_dinv[N_NODES];
__device__ int   g_csrc[N_EDGES];
__device__ float g_h1[(size_t)N_NODES * H];   // x @ W1
__device__ float g_h2[(size_t)N_NODES * H];   // relu(agg1+b1) @ W2

// ---------------- side stream + events (created at load time) ----------------
static cudaStream_t s2;
static cudaEvent_t  evFork, evJoin;
static struct StreamInit {
    StreamInit() {
        cudaStreamCreateWithFlags(&s2, cudaStreamNonBlocking);
        cudaEventCreateWithFlags(&evFork, cudaEventDisableTiming);
        cudaEventCreateWithFlags(&evJoin, cudaEventDisableTiming);
    }
} s_init;

// ---------------- zero degrees + int64-vs-int32 detection ----------------
__global__ void k_pre(const void* ei) {
    int i = blockIdx.x * blockDim.x + threadIdx.x;
    if (i < N_NODES) g_deg[i] = 0;
    if (i == 0) {
        const long long* p = (const long long*)ei;
        int ok = 1;
        for (int t = 0; t < 64; ++t) {
            long long v = p[t];
            if (v < 0 || v >= N_NODES) { ok = 0; break; }
        }
        g_is64 = ok;
    }
}

__device__ __forceinline__ int load_idx(const void* ei, int pos, int which) {
    if (g_is64) return (int)((const long long*)ei)[(size_t)which * N_EDGES + pos];
    return ((const int*)ei)[(size_t)which * N_EDGES + pos];
}

__global__ void k_hist(const void* __restrict__ ei) {
    int e = blockIdx.x * blockDim.x + threadIdx.x;
    if (e < N_EDGES) atomicAdd(&g_deg[load_idx(ei, e, 1)], 1);
}

// ---------------- exclusive scan of degrees (3 kernels) + dinv ----------------
__global__ void __launch_bounds__(256) k_scan1() {
    int i = blockIdx.x * 256 + threadIdx.x;
    int v = (i < N_NODES) ? g_deg[i] : 0;
    int lane = threadIdx.x & 31, w = threadIdx.x >> 5;
    int incl = v;
#pragma unroll
    for (int o = 1; o < 32; o <<= 1) {
        int t = __shfl_up_sync(0xffffffffu, incl, o);
        if (lane >= o) incl += t;
    }
    __shared__ int ws[8];
    if (lane == 31) ws[w] = incl;
    __syncthreads();
    if (w == 0 && lane < 8) {
        int t = ws[lane];
        int inc = t;
#pragma unroll
        for (int o = 1; o < 8; o <<= 1) {
            int u = __shfl_up_sync(0xffu, inc, o);
            if (lane >= o) inc += u;
        }
        ws[lane] = inc - t;  // exclusive warp base
    }
    __syncthreads();
    int excl = incl - v + ws[w];
    if (i < N_NODES) {
        g_off[i] = excl;
        g_dinv[i] = rsqrtf((float)(v + 1));  // +1 self-loop
    }
    if (threadIdx.x == 255) g_bsum[blockIdx.x] = excl + v;
}

__global__ void __launch_bounds__(512) k_scan2() {
    __shared__ int buf[512];
    int t = threadIdx.x;
    int v = (t < NB_SCAN) ? g_bsum[t] : 0;
    buf[t] = v;
    __syncthreads();
    for (int o = 1; o < 512; o <<= 1) {
        int u = (t >= o) ? buf[t - o] : 0;
        __syncthreads();
        buf[t] += u;
        __syncthreads();
    }
    if (t < NB_SCAN) g_bsum[t] = buf[t] - v;  // exclusive
}

__global__ void __launch_bounds__(256) k_scan3() {
    int i = blockIdx.x * 256 + threadIdx.x;
    if (i < N_NODES) {
        int o = g_off[i] + g_bsum[blockIdx.x];
        g_off[i] = o;
        g_cur[i] = o;
    }
}

// ---------------- CSR scatter (int atomics only) ----------------
__global__ void k_scatter(const void* __restrict__ ei) {
    int e = blockIdx.x * blockDim.x + threadIdx.x;
    if (e < N_EDGES) {
        int s = load_idx(ei, e, 0);
        int d = load_idx(ei, e, 1);
        int pos = atomicAdd(&g_cur[d], 1);
        g_csrc[pos] = s;
    }
}

// ---------------- GEMM1: register-tiled 64x64 tile per CTA (proven R12) ------
__global__ void __launch_bounds__(256) k_gemm1(const float* __restrict__ x,
                                               const float* __restrict__ W1) {
    extern __shared__ float dsm[];
    float* Ws = dsm;                 // 8192 floats
    float* xs = dsm + F_IN * H;      // 8192 floats

    int tid = threadIdx.x;
    int r0 = blockIdx.x * G1_TILE;

#pragma unroll
    for (int i = 0; i < (F_IN * H) / (256 * 4); ++i) {
        int idx = (i * 256 + tid) * 4;
        *(float4*)&Ws[idx] = *(const float4*)&W1[idx];
    }
#pragma unroll
    for (int i = 0; i < (G1_TILE * F_IN) / (256 * 4); ++i) {
        int t = i * 256 + tid;
        int row = t >> 5;
        int c4 = (t & 31) << 2;
        int r = r0 + row;
        float4 v = make_float4(0.f, 0.f, 0.f, 0.f);
        if (r < N_NODES) v = *(const float4*)&x[(size_t)r * F_IN + c4];
        *(float4*)&xs[row * F_IN + c4] = v;
    }
    __syncthreads();

    int ty = tid >> 4, tx = tid & 15;
    float acc[4][4] = {};

#pragma unroll 4
    for (int k4 = 0; k4 < F_IN / 4; ++k4) {
        float4 xv[4], wv[4];
#pragma unroll
        for (int i = 0; i < 4; ++i)
            xv[i] = *(const float4*)&xs[(ty * 4 + i) * F_IN + k4 * 4];
#pragma unroll
        for (int kk = 0; kk < 4; ++kk)
            wv[kk] = *(const float4*)&Ws[(k4 * 4 + kk) * H + tx * 4];
#pragma unroll
        for (int i = 0; i < 4; ++i) {
            float4 a = xv[i];
            acc[i][0] += a.x * wv[0].x + a.y * wv[1].x + a.z * wv[2].x + a.w * wv[3].x;
            acc[i][1] += a.x * wv[0].y + a.y * wv[1].y + a.z * wv[2].y + a.w * wv[3].y;
            acc[i][2] += a.x * wv[0].z + a.y * wv[1].z + a.z * wv[2].z + a.w * wv[3].z;
            acc[i][3] += a.x * wv[0].w + a.y * wv[1].w + a.z * wv[2].w + a.w * wv[3].w;
        }
    }

#pragma unroll
    for (int i = 0; i < 4; ++i) {
        int r = r0 + ty * 4 + i;
        if (r < N_NODES)
            *(float4*)&g_h1[(size_t)r * H + tx * 4] =
                make_float4(acc[i][0], acc[i][1], acc[i][2], acc[i][3]);
    }
}

// ---------------- layer1: EXACT R2/R8/R12 kernel ----------------
__global__ void __launch_bounds__(256) k_layer1(const float* __restrict__ W2,
                                                const float* __restrict__ b1) {
    __shared__ float W2s[H * H];  // 16 KB
    __shared__ float b1s[H];
    __shared__ float aS[8][H];
    int tid = threadIdx.x;
#pragma unroll
    for (int i = 0; i < (H * H) / 256; ++i) W2s[tid + i * 256] = W2[tid + i * 256];
    if (tid < H) b1s[tid] = b1[tid];
    __syncthreads();

    int w = tid >> 5, lane = tid & 31;
    int n = blockIdx.x * 8 + w;
    int c = lane << 1;

    float di = g_dinv[n];
    int row = g_off[n], deg = g_deg[n];

    float2 acc = *(const float2*)&g_h1[(size_t)n * H + c];
    float sl = di * di;
    acc.x *= sl; acc.y *= sl;

    const int* ep = g_csrc + row;
    for (int j = 0; j < deg; ++j) {
        int s = ep[j];
        float nm = g_dinv[s] * di;
        float2 v = *(const float2*)&g_h1[(size_t)s * H + c];
        acc.x += nm * v.x;
        acc.y += nm * v.y;
    }

    float a0 = fmaxf(acc.x + b1s[c], 0.f);
    float a1 = fmaxf(acc.y + b1s[c + 1], 0.f);
    aS[w][c] = a0;
    aS[w][c + 1] = a1;
    __syncwarp();

    float o0 = 0.f, o1 = 0.f;
#pragma unroll
    for (int k = 0; k < H; ++k) {
        float av = aS[w][k];
        float2 wv = *(const float2*)&W2s[k * H + c];
        o0 += av * wv.x;
        o1 += av * wv.y;
    }
    *(float2*)&g_h2[(size_t)n * H + c] = make_float2(o0, o1);
}

// ---------------- layer2: EXACT R2/R8/R12 kernel ----------------
__global__ void __launch_bounds__(256) k_layer2(const float* __restrict__ b2,
                                                const float* __restrict__ Wc,
                                                const float* __restrict__ bc,
                                                float* __restrict__ out) {
    __shared__ float WcS[H * C];  // 10.24 KB
    __shared__ float b2s[H];
    __shared__ float bcs[C];
    __shared__ float eS[8][H];
    int tid = threadIdx.x;
    for (int i = tid; i < H * C; i += 256) WcS[i] = Wc[i];
    if (tid < H) b2s[tid] = b2[tid];
    if (tid < C) bcs[tid] = bc[tid];
    __syncthreads();

    int w = tid >> 5, lane = tid & 31;
    int n = blockIdx.x * 8 + w;
    int c = lane << 1;

    const size_t embOff  = (size_t)N_NODES * C;
    const size_t softOff = embOff + (size_t)N_NODES * H;
    const size_t hardOff = softOff + (size_t)N_NODES * C;

    float di = g_dinv[n];
    int row = g_off[n], deg = g_deg[n];

    float2 acc = *(const float2*)&g_h2[(size_t)n * H + c];
    float sl = di * di;
    acc.x *= sl; acc.y *= sl;

    const int* ep = g_csrc + row;
    for (int j = 0; j < deg; ++j) {
        int s = ep[j];
        float nm = g_dinv[s] * di;
        float2 v = *(const float2*)&g_h2[(size_t)s * H + c];
        acc.x += nm * v.x;
        acc.y += nm * v.y;
    }
    acc.x += b2s[c];
    acc.y += b2s[c + 1];

    *(float2*)(out + embOff + (size_t)n * H + c) = acc;
    eS[w][c] = acc.x;
    eS[w][c + 1] = acc.y;
    __syncwarp();

    float acc0 = bcs[lane];
    float acc1 = (lane < 8) ? bcs[lane + 32] : 0.f;
#pragma unroll
    for (int k = 0; k < H; ++k) {
        float ev = eS[w][k];
        acc0 += ev * WcS[k * C + lane];
        if (lane < 8) acc1 += ev * WcS[k * C + lane + 32];
    }
    out[(size_t)n * C + lane] = acc0;
    if (lane < 8) out[(size_t)n * C + lane + 32] = acc1;

    float mv = acc0;
    int   mi = lane;
    if (lane < 8 && acc1 > mv) { mv = acc1; mi = lane + 32; }
#pragma unroll
    for (int o = 16; o; o >>= 1) {
        float ov = __shfl_xor_sync(0xffffffffu, mv, o);
        int   oi = __shfl_xor_sync(0xffffffffu, mi, o);
        if (ov > mv || (ov == mv && oi < mi)) { mv = ov; mi = oi; }
    }
    if (lane == 0) out[hardOff + n] = (float)mi;

    float e0 = expf(acc0 - mv);
    float e1 = (lane < 8) ? expf(acc1 - mv) : 0.f;
    float s = e0 + e1;
#pragma unroll
    for (int o = 16; o; o >>= 1) s += __shfl_xor_sync(0xffffffffu, s, o);
    float inv = 1.0f / s;
    out[softOff + (size_t)n * C + lane] = e0 * inv;
    if (lane < 8) out[softOff + (size_t)n * C + lane + 32] = e1 * inv;
}

// ---------------- launch: prep chain on origin stream, gemm1 forked on s2 ----
extern "C" void kernel_launch(void* const* d_in, const int* in_sizes, int n_in,
                              void* d_out, int out_size) {
    const float* x  = (const float*)d_in[0];
    const void*  ei = d_in[1];
    const float* W1 = (const float*)d_in[2];
    const float* b1 = (const float*)d_in[3];
    const float* W2 = (const float*)d_in[4];
    const float* b2 = (const float*)d_in[5];
    const float* Wc = (const float*)d_in[6];
    const float* bc = (const float*)d_in[7];
    float* out = (float*)d_out;

    cudaFuncSetAttribute(k_gemm1, cudaFuncAttributeMaxDynamicSharedMemorySize,
                         G1_SMEM);

    // fork: gemm1 (depends only on x, W1) runs on s2 in parallel with prep
    cudaEventRecord(evFork, 0);
    cudaStreamWaitEvent(s2, evFork, 0);
    k_gemm1<<<G1_GRID, 256, G1_SMEM, s2>>>(x, W1);
    cudaEventRecord(evJoin, s2);

    // graph prep chain on origin stream
    k_pre<<<(N_NODES + 255) / 256, 256>>>(ei);
    k_hist<<<(N_EDGES + 255) / 256, 256>>>(ei);
    k_scan1<<<NB_SCAN, 256>>>();
    k_scan2<<<1, 512>>>();
    k_scan3<<<NB_SCAN, 256>>>();
    k_scatter<<<(N_EDGES + 255) / 256, 256>>>(ei);

    // join: layers need both g_h1 (s2) and CSR (origin)
    cudaStreamWaitEvent(0, evJoin, 0);
    k_layer1<<<N_NODES / 8, 256>>>(W2, b1);
    k_layer2<<<N_NODES / 8, 256>>>(b2, Wc, bc, out);
}